// round 1
// baseline (speedup 1.0000x reference)
#include <cuda_runtime.h>
#include <math.h>

// Fused ConstrainedMLP: 262144 x (12 -> 256 relu -> 256 relu -> 12) + constraint epilogue.
// Strategy: 256 threads/CTA, 64 rows/CTA. h1/h2 in smem as [feature][row] (pad 66)
// so row-pairs feed packed fp32 FFMA2 (fma.rn.f32x2). W2 staged through smem in
// 32-row chunks to keep L2 traffic at 1 GB total.

#define BATCH   262144
#define ROWS    64      // rows per CTA
#define RP      66      // row pitch (floats) in h1s/h2s: even (8B align) + conflict-light
#define NTHREAD 256

typedef unsigned long long u64;

__device__ __forceinline__ u64 fma2(u64 a, u64 b, u64 c) {
    u64 d;
    asm("fma.rn.f32x2 %0, %1, %2, %3;" : "=l"(d) : "l"(a), "l"(b), "l"(c));
    return d;
}
__device__ __forceinline__ u64 pack2(float x, float y) {
    u64 r;
    asm("mov.b64 %0, {%1, %2};" : "=l"(r) : "f"(x), "f"(y));
    return r;
}
__device__ __forceinline__ void unpack2(u64 v, float& x, float& y) {
    asm("mov.b64 {%0, %1}, %2;" : "=f"(x), "=f"(y) : "l"(v));
}

// smem float offsets
#define OFF_XS    0                     // 64*12          = 768
#define OFF_W3    768                   // 256*12         = 3072
#define OFF_X12   3840                  // 64*12          = 768
#define OFF_H1    4608                  // 256*66         = 16896
#define OFF_H2    21504                 // 256*66         = 16896
#define OFF_W2C   38400                 // 32*256         = 8192
#define SMEM_FLOATS 46592               // *4 = 186368 bytes

__global__ __launch_bounds__(NTHREAD, 1)
void constrained_mlp_kernel(const float* __restrict__ inp,
                            const float* __restrict__ W1,
                            const float* __restrict__ b1,
                            const float* __restrict__ W2,
                            const float* __restrict__ b2,
                            const float* __restrict__ W3,
                            const float* __restrict__ b3,
                            float* __restrict__ out)
{
    extern __shared__ float sm[];
    float* xs   = sm + OFF_XS;
    float* w3s  = sm + OFF_W3;
    float* x12s = sm + OFF_X12;
    float* h1s  = sm + OFF_H1;
    float* h2s  = sm + OFF_H2;
    float* w2c  = sm + OFF_W2C;

    const int t = threadIdx.x;
    const long rowBase = (long)blockIdx.x * ROWS;

    // ---- cooperative loads: input tile + W3 ----
    const float* inpBlk = inp + rowBase * 12;
    for (int i = t; i < ROWS * 12; i += NTHREAD) xs[i] = inpBlk[i];
    for (int i = t; i < 256 * 12; i += NTHREAD) w3s[i] = W3[i];

    // ---- layer 1: thread t owns hidden unit j=t for all 64 rows ----
    float w1r[12];
#pragma unroll
    for (int k = 0; k < 12; k++) w1r[k] = W1[k * 256 + t];
    const float b1t = b1[t];
    const float b2t = b2[t];
    __syncthreads();

#pragma unroll 4
    for (int r = 0; r < ROWS; r++) {
        const float* xr = xs + r * 12;
        float acc = b1t;
#pragma unroll
        for (int k = 0; k < 12; k++) acc = fmaf(xr[k], w1r[k], acc);
        h1s[t * RP + r] = fmaxf(acc, 0.0f);
    }

    // init h2 accumulators (in smem) with bias
#pragma unroll 4
    for (int r = 0; r < ROWS; r++) h2s[t * RP + r] = b2t;
    __syncthreads();

    // ---- layer 2: thread t owns hidden unit j=t. k chunked by 32 through smem.
    //      Row pairs processed with packed fp32 FMA (fma.rn.f32x2).
    for (int c = 0; c < 8; c++) {
        const float* W2blk = W2 + c * 32 * 256;
#pragma unroll
        for (int i = 0; i < 32; i++) w2c[i * 256 + t] = W2blk[i * 256 + t];
        __syncthreads();

        const bool last = (c == 7);
#pragma unroll
        for (int rg = 0; rg < 4; rg++) {
            float* h2p = h2s + t * RP + rg * 16;
            u64 acc[8];
#pragma unroll
            for (int p = 0; p < 8; p++)
                acc[p] = *reinterpret_cast<u64*>(h2p + 2 * p);

#pragma unroll 8
            for (int kk = 0; kk < 32; kk++) {
                const float w = w2c[kk * 256 + t];
                const u64 wp = pack2(w, w);
                const float* hp = h1s + (c * 32 + kk) * RP + rg * 16;
#pragma unroll
                for (int p = 0; p < 8; p++)
                    acc[p] = fma2(*reinterpret_cast<const u64*>(hp + 2 * p), wp, acc[p]);
            }

            if (last) {
#pragma unroll
                for (int p = 0; p < 8; p++) {
                    float lo, hi;
                    unpack2(acc[p], lo, hi);
                    acc[p] = pack2(fmaxf(lo, 0.0f), fmaxf(hi, 0.0f));
                }
            }
#pragma unroll
            for (int p = 0; p < 8; p++)
                *reinterpret_cast<u64*>(h2p + 2 * p) = acc[p];
        }
        __syncthreads();
    }

    // ---- layer 3: thread t computes row r = t>>2, outputs og..og+2 where og=(t&3)*3
    {
        const int r  = t >> 2;
        const int og = (t & 3) * 3;
        float a0 = b3[og], a1 = b3[og + 1], a2 = b3[og + 2];
#pragma unroll 8
        for (int k = 0; k < 256; k++) {
            const float h  = h2s[k * RP + r];
            const float* w = w3s + k * 12 + og;
            a0 = fmaf(h, w[0], a0);
            a1 = fmaf(h, w[1], a1);
            a2 = fmaf(h, w[2], a2);
        }
        x12s[r * 12 + og + 0] = a0;
        x12s[r * 12 + og + 1] = a1;
        x12s[r * 12 + og + 2] = a2;
    }
    __syncthreads();

    // ---- constraint epilogue: one thread per row ----
    if (t < ROWS) {
        const float* xi = xs + t * 12;    // original input row
        const float* xo = x12s + t * 12;  // layer-3 pre-activation

        float p0 = tanhf(xo[0]), p1 = tanhf(xo[1]), p2 = tanhf(xo[2]);
        float v0 = tanhf(xo[3]), v1 = tanhf(xo[4]), v2 = tanhf(xo[5]);
        float pts = 1.0f / (1.0f + expf(-xo[6]));
        float c0 = tanhf(xo[7]), c1 = tanhf(xo[8]), c2 = tanhf(xo[9]);
        float s0 = tanhf(xo[10]), s1 = tanhf(xo[11]);

        // pos clamp to unit ball
        float dist = sqrtf(p0 * p0 + p1 * p1 + p2 * p2);
        float pinv = (dist > 1.0f) ? (1.0f / dist) : 1.0f;
        p0 *= pinv; p1 *= pinv; p2 *= pinv;

        // points monotonic clamp
        const float prev = xi[6];
        float ptsc = (pts > 1.0f) ? 1.0f : pts;
        ptsc = (pts < prev) ? prev : ptsc;

        // cluster constraint
        const float d0 = c0 - xi[7], d1 = c1 - xi[8], d2 = c2 - xi[9];
        const float e0 = xi[0] - xi[7], e1 = xi[1] - xi[8], e2 = xi[2] - xi[9];
        const float en = sqrtf(e0 * e0 + e1 * e1 + e2 * e2);
        const float n0 = e0 / en, n1 = e1 / en, n2 = e2 / en;
        const float dd = d0 * e0 + d1 * e1 + d2 * e2;
        const float o0 = (dd > 0.0f) ? (c0 - n0) : c0;
        const float o1 = (dd > 0.0f) ? (c1 - n1) : c1;
        const float o2 = (dd > 0.0f) ? (c2 - n2) : c2;
        const float cd = sqrtf(o0 * o0 + o1 * o1 + o2 * o2);
        float q0, q1, q2;
        if (cd > 1.0f) { const float ci = 1.0f / cd; q0 = o0 * ci; q1 = o1 * ci; q2 = o2 * ci; }
        else           { q0 = c0; q1 = c1; q2 = c2; }

        // sun normalize
        const float sn = sqrtf(s0 * s0 + s1 * s1);
        s0 /= sn; s1 /= sn;

        float* op = out + (rowBase + t) * 12;
        float4* ov = reinterpret_cast<float4*>(op);
        ov[0] = make_float4(p0, p1, p2, v0);
        ov[1] = make_float4(v1, v2, ptsc, q0);
        ov[2] = make_float4(q1, q2, s0, s1);
    }
}

extern "C" void kernel_launch(void* const* d_in, const int* in_sizes, int n_in,
                              void* d_out, int out_size)
{
    (void)in_sizes; (void)n_in; (void)out_size;
    const float* inp = (const float*)d_in[0];
    const float* W1  = (const float*)d_in[1];
    const float* b1  = (const float*)d_in[2];
    const float* W2  = (const float*)d_in[3];
    const float* b2  = (const float*)d_in[4];
    const float* W3  = (const float*)d_in[5];
    const float* b3  = (const float*)d_in[6];
    float* out = (float*)d_out;

    const size_t smem = SMEM_FLOATS * sizeof(float);
    cudaFuncSetAttribute(constrained_mlp_kernel,
                         cudaFuncAttributeMaxDynamicSharedMemorySize, (int)smem);
    const int grid = BATCH / ROWS;  // 4096
    constrained_mlp_kernel<<<grid, NTHREAD, smem>>>(inp, W1, b1, W2, b2, W3, b3, out);
}

// round 2
// speedup vs baseline: 1.2530x; 1.2530x over previous
#include <cuda_runtime.h>
#include <math.h>

// Fused ConstrainedMLP: 262144 x (12 -> 256 relu -> 256 relu -> 12) + constraint epilogue.
// R2: 128 threads/CTA, 64 rows/CTA, 2 hidden units per thread, LDS.128 h1 reads,
// packed fp32 FFMA2 everywhere, cp.async double-buffered W2 staging.

#define BATCH   262144
#define ROWS    64
#define RP      68      // row pitch (floats): mult of 4 for LDS.128 alignment
#define NTHREAD 128

typedef unsigned long long u64;

__device__ __forceinline__ u64 fma2(u64 a, u64 b, u64 c) {
    u64 d;
    asm("fma.rn.f32x2 %0, %1, %2, %3;" : "=l"(d) : "l"(a), "l"(b), "l"(c));
    return d;
}
__device__ __forceinline__ u64 pack2(float x, float y) {
    u64 r;
    asm("mov.b64 %0, {%1, %2};" : "=l"(r) : "f"(x), "f"(y));
    return r;
}
__device__ __forceinline__ void unpack2(u64 v, float& x, float& y) {
    asm("mov.b64 {%0, %1}, %2;" : "=f"(x), "=f"(y) : "l"(v));
}
__device__ __forceinline__ void cp_async16(float* smem_dst, const float4* gsrc) {
    unsigned saddr = (unsigned)__cvta_generic_to_shared(smem_dst);
    asm volatile("cp.async.cg.shared.global [%0], [%1], 16;" :: "r"(saddr), "l"(gsrc));
}
__device__ __forceinline__ void cp_commit() { asm volatile("cp.async.commit_group;"); }
__device__ __forceinline__ void cp_wait0()  { asm volatile("cp.async.wait_group 0;" ::: "memory"); }

// smem float offsets
#define OFF_XS    0                     // 64*12            = 768
#define OFF_W3    768                   // 256*12           = 3072
#define OFF_X12   3840                  // 64*12            = 768
#define OFF_H1    4608                  // 256*68           = 17408
#define OFF_H2    22016                 // 256*68           = 17408
#define OFF_W2C   39424                 // 2 * 32*256       = 16384 (buf0 aliases W1+b1)
#define SMEM_FLOATS 55808               // *4 = 223232 bytes

__global__ __launch_bounds__(NTHREAD, 1)
void constrained_mlp_kernel(const float* __restrict__ inp,
                            const float* __restrict__ W1,
                            const float* __restrict__ b1,
                            const float* __restrict__ W2,
                            const float* __restrict__ b2,
                            const float* __restrict__ W3,
                            const float* __restrict__ b3,
                            float* __restrict__ out)
{
    extern __shared__ float sm[];
    float* xs   = sm + OFF_XS;
    float* w3s  = sm + OFF_W3;
    float* x12s = sm + OFF_X12;
    float* h1s  = sm + OFF_H1;
    float* h2s  = sm + OFF_H2;
    float* w2c  = sm + OFF_W2C;      // double buffer: [0]=w2c, [1]=w2c+8192

    const int t = threadIdx.x;
    const long rowBase = (long)blockIdx.x * ROWS;

    // per-thread biases for the 2 owned hidden units of layer 2
    const float b2t0 = b2[t];
    const float b2t1 = b2[t + 128];

    // ---- cooperative staging: input tile, W3, W1+b1 (W1 aliased into w2c buf0) ----
    float* w1s = w2c;          // 12*256 = 3072
    float* b1s = w2c + 3072;   // 256
    const float* inpBlk = inp + rowBase * 12;
    for (int i = t; i < ROWS * 12; i += NTHREAD) xs[i]  = inpBlk[i];
    for (int i = t; i < 256 * 12; i += NTHREAD)  w3s[i] = W3[i];
    for (int i = t; i < 12 * 256; i += NTHREAD)  w1s[i] = W1[i];
    for (int i = t; i < 256; i += NTHREAD)       b1s[i] = b1[i];
    __syncthreads();

    // ---- prefetch W2 chunk 0 into buf1 while layer 1 runs ----
    {
        const float4* g = reinterpret_cast<const float4*>(W2);  // chunk 0
        float* s = w2c + 8192;
#pragma unroll
        for (int k = 0; k < 16; k++)
            cp_async16(s + (t + k * 128) * 4, g + t + k * 128);
        cp_commit();
    }

    // ---- layer 1 (row-owner): thread t handles row r for 128 hidden units ----
    {
        const int r    = t & 63;
        const int half = t >> 6;
        const int j0   = half * 128;
        float xr[12];
        const float4* xv = reinterpret_cast<const float4*>(xs + r * 12);
        float4 x0 = xv[0], x1 = xv[1], x2 = xv[2];
        xr[0]=x0.x; xr[1]=x0.y; xr[2]=x0.z; xr[3]=x0.w;
        xr[4]=x1.x; xr[5]=x1.y; xr[6]=x1.z; xr[7]=x1.w;
        xr[8]=x2.x; xr[9]=x2.y; xr[10]=x2.z; xr[11]=x2.w;
#pragma unroll 4
        for (int j = 0; j < 128; j++) {
            const int jj = j0 + j;
            float acc = b1s[jj];
#pragma unroll
            for (int k = 0; k < 12; k++) acc = fmaf(xr[k], w1s[k * 256 + jj], acc);
            h1s[jj * RP + r] = fmaxf(acc, 0.0f);   // lanes write consecutive r: conflict-free
        }
    }
    __syncthreads();   // h1 complete; w1s (buf0) free for reuse

    // ---- layer 2: thread t owns j0=t, j1=t+128; acc spilled to h2s between chunks ----
    for (int c = 0; c < 8; c++) {
        cp_wait0();
        __syncthreads();                       // chunk c ready in buf[(c+1)&1]
        if (c < 7) {
            const float4* g = reinterpret_cast<const float4*>(W2) + (c + 1) * 2048;
            float* s = w2c + 8192 * (c & 1);
#pragma unroll
            for (int k = 0; k < 16; k++)
                cp_async16(s + (t + k * 128) * 4, g + t + k * 128);
            cp_commit();
        }
        const float* wb = w2c + 8192 * ((c + 1) & 1);
        const bool first = (c == 0);
        const bool last  = (c == 7);

#pragma unroll
        for (int rg = 0; rg < 4; rg++) {
            float* h2p0 = h2s + t * RP + rg * 16;
            float* h2p1 = h2s + (t + 128) * RP + rg * 16;
            u64 a0[8], a1[8];
            if (first) {
                const u64 bb0 = pack2(b2t0, b2t0);
                const u64 bb1 = pack2(b2t1, b2t1);
#pragma unroll
                for (int p = 0; p < 8; p++) { a0[p] = bb0; a1[p] = bb1; }
            } else {
#pragma unroll
                for (int p = 0; p < 4; p++) {
                    ulonglong2 v0 = *reinterpret_cast<ulonglong2*>(h2p0 + 4 * p);
                    ulonglong2 v1 = *reinterpret_cast<ulonglong2*>(h2p1 + 4 * p);
                    a0[2*p] = v0.x; a0[2*p+1] = v0.y;
                    a1[2*p] = v1.x; a1[2*p+1] = v1.y;
                }
            }

#pragma unroll
            for (int kk = 0; kk < 32; kk++) {
                const float w0 = wb[kk * 256 + t];
                const float w1v = wb[kk * 256 + 128 + t];
                const u64 wp0 = pack2(w0, w0);
                const u64 wp1 = pack2(w1v, w1v);
                const float* hp = h1s + (c * 32 + kk) * RP + rg * 16;
#pragma unroll
                for (int p = 0; p < 4; p++) {
                    ulonglong2 hv = *reinterpret_cast<const ulonglong2*>(hp + 4 * p);
                    a0[2*p]   = fma2(hv.x, wp0, a0[2*p]);
                    a0[2*p+1] = fma2(hv.y, wp0, a0[2*p+1]);
                    a1[2*p]   = fma2(hv.x, wp1, a1[2*p]);
                    a1[2*p+1] = fma2(hv.y, wp1, a1[2*p+1]);
                }
            }

            if (last) {
#pragma unroll
                for (int p = 0; p < 8; p++) {
                    float lo, hi;
                    unpack2(a0[p], lo, hi);
                    a0[p] = pack2(fmaxf(lo, 0.0f), fmaxf(hi, 0.0f));
                    unpack2(a1[p], lo, hi);
                    a1[p] = pack2(fmaxf(lo, 0.0f), fmaxf(hi, 0.0f));
                }
            }
#pragma unroll
            for (int p = 0; p < 4; p++) {
                ulonglong2 v0; v0.x = a0[2*p]; v0.y = a0[2*p+1];
                ulonglong2 v1; v1.x = a1[2*p]; v1.y = a1[2*p+1];
                *reinterpret_cast<ulonglong2*>(h2p0 + 4 * p) = v0;
                *reinterpret_cast<ulonglong2*>(h2p1 + 4 * p) = v1;
            }
        }
    }
    __syncthreads();

    // ---- layer 3: thread t -> row r = t>>1, outputs og..og+5 where og=(t&1)*6 ----
    {
        const int r  = t >> 1;
        const int og = (t & 1) * 6;
        u64 a[3];
#pragma unroll
        for (int i = 0; i < 3; i++) a[i] = pack2(b3[og + 2*i], b3[og + 2*i + 1]);
#pragma unroll 8
        for (int k = 0; k < 256; k++) {
            const float h = h2s[k * RP + r];
            const u64 hh = pack2(h, h);
            const u64* w = reinterpret_cast<const u64*>(w3s + k * 12 + og);
            a[0] = fma2(w[0], hh, a[0]);
            a[1] = fma2(w[1], hh, a[1]);
            a[2] = fma2(w[2], hh, a[2]);
        }
        u64* xo = reinterpret_cast<u64*>(x12s + r * 12 + og);
        xo[0] = a[0]; xo[1] = a[1]; xo[2] = a[2];
    }
    __syncthreads();

    // ---- constraint epilogue: one thread per row ----
    if (t < ROWS) {
        const float* xi = xs + t * 12;
        const float* xo = x12s + t * 12;

        float p0 = tanhf(xo[0]), p1 = tanhf(xo[1]), p2 = tanhf(xo[2]);
        float v0 = tanhf(xo[3]), v1 = tanhf(xo[4]), v2 = tanhf(xo[5]);
        float pts = 1.0f / (1.0f + expf(-xo[6]));
        float c0 = tanhf(xo[7]), c1 = tanhf(xo[8]), c2 = tanhf(xo[9]);
        float s0 = tanhf(xo[10]), s1 = tanhf(xo[11]);

        float dist = sqrtf(p0 * p0 + p1 * p1 + p2 * p2);
        float pinv = (dist > 1.0f) ? (1.0f / dist) : 1.0f;
        p0 *= pinv; p1 *= pinv; p2 *= pinv;

        const float prev = xi[6];
        float ptsc = (pts > 1.0f) ? 1.0f : pts;
        ptsc = (pts < prev) ? prev : ptsc;

        const float d0 = c0 - xi[7], d1 = c1 - xi[8], d2 = c2 - xi[9];
        const float e0 = xi[0] - xi[7], e1 = xi[1] - xi[8], e2 = xi[2] - xi[9];
        const float en = sqrtf(e0 * e0 + e1 * e1 + e2 * e2);
        const float n0 = e0 / en, n1 = e1 / en, n2 = e2 / en;
        const float dd = d0 * e0 + d1 * e1 + d2 * e2;
        const float o0 = (dd > 0.0f) ? (c0 - n0) : c0;
        const float o1 = (dd > 0.0f) ? (c1 - n1) : c1;
        const float o2 = (dd > 0.0f) ? (c2 - n2) : c2;
        const float cd = sqrtf(o0 * o0 + o1 * o1 + o2 * o2);
        float q0, q1, q2;
        if (cd > 1.0f) { const float ci = 1.0f / cd; q0 = o0 * ci; q1 = o1 * ci; q2 = o2 * ci; }
        else           { q0 = c0; q1 = c1; q2 = c2; }

        const float sn = sqrtf(s0 * s0 + s1 * s1);
        s0 /= sn; s1 /= sn;

        float* op = out + (rowBase + t) * 12;
        float4* ov = reinterpret_cast<float4*>(op);
        ov[0] = make_float4(p0, p1, p2, v0);
        ov[1] = make_float4(v1, v2, ptsc, q0);
        ov[2] = make_float4(q1, q2, s0, s1);
    }
}

extern "C" void kernel_launch(void* const* d_in, const int* in_sizes, int n_in,
                              void* d_out, int out_size)
{
    (void)in_sizes; (void)n_in; (void)out_size;
    const float* inp = (const float*)d_in[0];
    const float* W1  = (const float*)d_in[1];
    const float* b1  = (const float*)d_in[2];
    const float* W2  = (const float*)d_in[3];
    const float* b2  = (const float*)d_in[4];
    const float* W3  = (const float*)d_in[5];
    const float* b3  = (const float*)d_in[6];
    float* out = (float*)d_out;

    const size_t smem = SMEM_FLOATS * sizeof(float);
    cudaFuncSetAttribute(constrained_mlp_kernel,
                         cudaFuncAttributeMaxDynamicSharedMemorySize, (int)smem);
    const int grid = BATCH / ROWS;  // 4096
    constrained_mlp_kernel<<<grid, NTHREAD, smem>>>(inp, W1, b1, W2, b2, W3, b3, out);
}

// round 3
// speedup vs baseline: 1.8006x; 1.4370x over previous
#include <cuda_runtime.h>
#include <math.h>

// Fused ConstrainedMLP: 262144 x (12 -> 256 relu -> 256 relu -> 12) + constraint epilogue.
// R3: 128 threads/CTA, 32 rows/CTA, 2 CTAs/SM (8 warps/SM). Layer-2 accumulators
// (2 units x 16 row-pairs = 32 u64) fully register-resident across k. FFMA2 packed
// fp32 math, cp.async double-buffered W2 staging in 16-k chunks.

#define BATCH   262144
#define ROWS    32
#define NTHREAD 128
#define H2P     260      // h2 pitch [row][j]: 256 + 4 pad
#define CHUNK   16       // k per W2 stage chunk
#define NCHUNK  16

typedef unsigned long long u64;

__device__ __forceinline__ u64 fma2(u64 a, u64 b, u64 c) {
    u64 d;
    asm("fma.rn.f32x2 %0, %1, %2, %3;" : "=l"(d) : "l"(a), "l"(b), "l"(c));
    return d;
}
__device__ __forceinline__ u64 pack2(float x, float y) {
    u64 r;
    asm("mov.b64 %0, {%1, %2};" : "=l"(r) : "f"(x), "f"(y));
    return r;
}
__device__ __forceinline__ void unpack2(u64 v, float& x, float& y) {
    asm("mov.b64 {%0, %1}, %2;" : "=f"(x), "=f"(y) : "l"(v));
}
__device__ __forceinline__ void cp_async16(float* smem_dst, const float4* gsrc) {
    unsigned saddr = (unsigned)__cvta_generic_to_shared(smem_dst);
    asm volatile("cp.async.cg.shared.global [%0], [%1], 16;" :: "r"(saddr), "l"(gsrc));
}
__device__ __forceinline__ void cp_commit() { asm volatile("cp.async.commit_group;"); }
__device__ __forceinline__ void cp_wait0()  { asm volatile("cp.async.wait_group 0;" ::: "memory"); }

// smem float offsets
#define OFF_XS    0        // 32*12          = 384
#define OFF_W3    384      // 256*12         = 3072
#define OFF_X12   3456     // 32*12          = 384
#define OFF_H1    3840     // 256*32         = 8192   (pitch 32, broadcast reads)
#define OFF_H2    12032    // 32*260         = 8320   ([row][j] layout)
#define OFF_W2C   20352    // 2 * 16*256     = 8192   (buf0 aliases W1t+b1)
#define SMEM_FLOATS 28544  // *4 = 114176 bytes -> 2 CTAs/SM

__global__ __launch_bounds__(NTHREAD, 2)
void constrained_mlp_kernel(const float* __restrict__ inp,
                            const float* __restrict__ W1,
                            const float* __restrict__ b1,
                            const float* __restrict__ W2,
                            const float* __restrict__ b2,
                            const float* __restrict__ W3,
                            const float* __restrict__ b3,
                            float* __restrict__ out)
{
    extern __shared__ float sm[];
    float* xs   = sm + OFF_XS;
    float* w3s  = sm + OFF_W3;
    float* x12s = sm + OFF_X12;
    float* h1s  = sm + OFF_H1;
    float* h2t  = sm + OFF_H2;
    float* w2c  = sm + OFF_W2C;      // double buffer: [0]=w2c, [1]=w2c+4096

    const int t = threadIdx.x;
    const long rowBase = (long)blockIdx.x * ROWS;

    const float b2t0 = b2[t];
    const float b2t1 = b2[t + 128];

    // ---- staging: input tile, W3, W1 transposed [j][k] + b1 (aliased into w2c buf0) ----
    float* w1t = w2c;          // 256*12 = 3072
    float* b1s = w2c + 3072;   // 256
    const float* inpBlk = inp + rowBase * 12;
    for (int i = t; i < ROWS * 12; i += NTHREAD) xs[i]  = inpBlk[i];
    for (int i = t; i < 256 * 12; i += NTHREAD)  w3s[i] = W3[i];
    for (int i = t; i < 12 * 256; i += NTHREAD) {
        const int k = i / 256, j = i % 256;
        w1t[j * 12 + k] = W1[i];
    }
    for (int i = t; i < 256; i += NTHREAD) b1s[i] = b1[i];
    __syncthreads();

    // ---- prefetch W2 chunk 0 into buf1 while layer 1 runs ----
    {
        const float4* g = reinterpret_cast<const float4*>(W2);  // chunk 0: 1024 float4
        float* s = w2c + 4096;
#pragma unroll
        for (int k = 0; k < 8; k++)
            cp_async16(s + (t + k * 128) * 4, g + t + k * 128);
        cp_commit();
    }

    // ---- layer 1: warp w handles j in [64w, 64w+64); lane = row r ----
    {
        const int r  = t & 31;
        const int j0 = (t >> 5) * 64;
        float xr[12];
        const float4* xv = reinterpret_cast<const float4*>(xs + r * 12);
        float4 x0 = xv[0], x1 = xv[1], x2 = xv[2];
        xr[0]=x0.x; xr[1]=x0.y; xr[2]=x0.z; xr[3]=x0.w;
        xr[4]=x1.x; xr[5]=x1.y; xr[6]=x1.z; xr[7]=x1.w;
        xr[8]=x2.x; xr[9]=x2.y; xr[10]=x2.z; xr[11]=x2.w;
#pragma unroll 4
        for (int j = 0; j < 64; j++) {
            const int jj = j0 + j;
            const float4* wv = reinterpret_cast<const float4*>(w1t + jj * 12);
            float4 w0 = wv[0], w1v = wv[1], w2v = wv[2];
            float acc = b1s[jj];
            acc = fmaf(xr[0], w0.x, acc);  acc = fmaf(xr[1], w0.y, acc);
            acc = fmaf(xr[2], w0.z, acc);  acc = fmaf(xr[3], w0.w, acc);
            acc = fmaf(xr[4], w1v.x, acc); acc = fmaf(xr[5], w1v.y, acc);
            acc = fmaf(xr[6], w1v.z, acc); acc = fmaf(xr[7], w1v.w, acc);
            acc = fmaf(xr[8], w2v.x, acc); acc = fmaf(xr[9], w2v.y, acc);
            acc = fmaf(xr[10], w2v.z, acc); acc = fmaf(xr[11], w2v.w, acc);
            h1s[jj * 32 + r] = fmaxf(acc, 0.0f);   // consecutive r per lane: conflict-free
        }
    }
    __syncthreads();   // h1 complete; buf0 (w1t) free for chunk staging

    // ---- layer 2: thread t owns j0=t, j1=t+128; 32 u64 accs resident in regs ----
    u64 A0[16], A1[16];
    {
        const u64 bb0 = pack2(b2t0, b2t0);
        const u64 bb1 = pack2(b2t1, b2t1);
#pragma unroll
        for (int p = 0; p < 16; p++) { A0[p] = bb0; A1[p] = bb1; }
    }

    for (int c = 0; c < NCHUNK; c++) {
        cp_wait0();
        __syncthreads();                        // chunk c ready in buf[(c+1)&1]
        if (c < NCHUNK - 1) {
            const float4* g = reinterpret_cast<const float4*>(W2) + (c + 1) * 1024;
            float* s = w2c + 4096 * (c & 1);
#pragma unroll
            for (int k = 0; k < 8; k++)
                cp_async16(s + (t + k * 128) * 4, g + t + k * 128);
            cp_commit();
        }
        const float* wb = w2c + 4096 * ((c + 1) & 1);

#pragma unroll
        for (int kk = 0; kk < CHUNK; kk++) {
            const float w0  = wb[kk * 256 + t];
            const float w1v = wb[kk * 256 + 128 + t];
            const u64 wp0 = pack2(w0, w0);
            const u64 wp1 = pack2(w1v, w1v);
            const float* hp = h1s + (c * CHUNK + kk) * 32;
#pragma unroll
            for (int p = 0; p < 8; p++) {
                const ulonglong2 hv = *reinterpret_cast<const ulonglong2*>(hp + 4 * p);
                A0[2*p]   = fma2(hv.x, wp0, A0[2*p]);
                A0[2*p+1] = fma2(hv.y, wp0, A0[2*p+1]);
                A1[2*p]   = fma2(hv.x, wp1, A1[2*p]);
                A1[2*p+1] = fma2(hv.y, wp1, A1[2*p+1]);
            }
        }
    }

    // relu + write h2 transposed [row][j] (lanes write consecutive j: conflict-free)
#pragma unroll
    for (int p = 0; p < 16; p++) {
        float lo, hi;
        unpack2(A0[p], lo, hi);
        h2t[(2*p)   * H2P + t] = fmaxf(lo, 0.0f);
        h2t[(2*p+1) * H2P + t] = fmaxf(hi, 0.0f);
        unpack2(A1[p], lo, hi);
        h2t[(2*p)   * H2P + 128 + t] = fmaxf(lo, 0.0f);
        h2t[(2*p+1) * H2P + 128 + t] = fmaxf(hi, 0.0f);
    }
    __syncthreads();

    // ---- layer 3: thread t -> row r = t>>2, outputs og..og+2, og=(t&3)*3 ----
    {
        const int r  = t >> 2;
        const int og = (t & 3) * 3;
        const float* hrow = h2t + r * H2P;
        float a0 = b3[og], a1 = b3[og + 1], a2 = b3[og + 2];
#pragma unroll 8
        for (int k = 0; k < 256; k++) {
            const float h  = hrow[k];
            const float* w = w3s + k * 12 + og;
            a0 = fmaf(h, w[0], a0);
            a1 = fmaf(h, w[1], a1);
            a2 = fmaf(h, w[2], a2);
        }
        x12s[r * 12 + og + 0] = a0;
        x12s[r * 12 + og + 1] = a1;
        x12s[r * 12 + og + 2] = a2;
    }
    __syncthreads();

    // ---- constraint epilogue: one thread per row ----
    if (t < ROWS) {
        const float* xi = xs + t * 12;
        const float* xo = x12s + t * 12;

        float p0 = tanhf(xo[0]), p1 = tanhf(xo[1]), p2 = tanhf(xo[2]);
        float v0 = tanhf(xo[3]), v1 = tanhf(xo[4]), v2 = tanhf(xo[5]);
        float pts = 1.0f / (1.0f + expf(-xo[6]));
        float c0 = tanhf(xo[7]), c1 = tanhf(xo[8]), c2 = tanhf(xo[9]);
        float s0 = tanhf(xo[10]), s1 = tanhf(xo[11]);

        float dist = sqrtf(p0 * p0 + p1 * p1 + p2 * p2);
        float pinv = (dist > 1.0f) ? (1.0f / dist) : 1.0f;
        p0 *= pinv; p1 *= pinv; p2 *= pinv;

        const float prev = xi[6];
        float ptsc = (pts > 1.0f) ? 1.0f : pts;
        ptsc = (pts < prev) ? prev : ptsc;

        const float d0 = c0 - xi[7], d1 = c1 - xi[8], d2 = c2 - xi[9];
        const float e0 = xi[0] - xi[7], e1 = xi[1] - xi[8], e2 = xi[2] - xi[9];
        const float en = sqrtf(e0 * e0 + e1 * e1 + e2 * e2);
        const float n0 = e0 / en, n1 = e1 / en, n2 = e2 / en;
        const float dd = d0 * e0 + d1 * e1 + d2 * e2;
        const float o0 = (dd > 0.0f) ? (c0 - n0) : c0;
        const float o1 = (dd > 0.0f) ? (c1 - n1) : c1;
        const float o2 = (dd > 0.0f) ? (c2 - n2) : c2;
        const float cd = sqrtf(o0 * o0 + o1 * o1 + o2 * o2);
        float q0, q1, q2;
        if (cd > 1.0f) { const float ci = 1.0f / cd; q0 = o0 * ci; q1 = o1 * ci; q2 = o2 * ci; }
        else           { q0 = c0; q1 = c1; q2 = c2; }

        const float sn = sqrtf(s0 * s0 + s1 * s1);
        s0 /= sn; s1 /= sn;

        float* op = out + (rowBase + t) * 12;
        float4* ov = reinterpret_cast<float4*>(op);
        ov[0] = make_float4(p0, p1, p2, v0);
        ov[1] = make_float4(v1, v2, ptsc, q0);
        ov[2] = make_float4(q1, q2, s0, s1);
    }
}

extern "C" void kernel_launch(void* const* d_in, const int* in_sizes, int n_in,
                              void* d_out, int out_size)
{
    (void)in_sizes; (void)n_in; (void)out_size;
    const float* inp = (const float*)d_in[0];
    const float* W1  = (const float*)d_in[1];
    const float* b1  = (const float*)d_in[2];
    const float* W2  = (const float*)d_in[3];
    const float* b2  = (const float*)d_in[4];
    const float* W3  = (const float*)d_in[5];
    const float* b3  = (const float*)d_in[6];
    float* out = (float*)d_out;

    const size_t smem = SMEM_FLOATS * sizeof(float);
    cudaFuncSetAttribute(constrained_mlp_kernel,
                         cudaFuncAttributeMaxDynamicSharedMemorySize, (int)smem);
    const int grid = BATCH / ROWS;  // 8192
    constrained_mlp_kernel<<<grid, NTHREAD, smem>>>(inp, W1, b1, W2, b2, W3, b3, out);
}

// round 5
// speedup vs baseline: 3.4286x; 1.9041x over previous
#include <cuda_runtime.h>
#include <cuda_bf16.h>
#include <math.h>
#include <stdint.h>

// Fused ConstrainedMLP: 262144 x (12 -> 256 relu -> 256 relu -> 12) + constraints.
// Layer 2 via mma.sync.m16n8k16 bf16 (sm_100 baseline ISA), 3-term hi/lo split.
// CTA: 128 rows, 512 threads (16 warps: 4M x 4N, warp tile m32n64), K chunked by 64,
// W2^T pre-split/swizzled by prep kernel, cp.async double-buffered.

#define BATCH    262144
#define TROWS    128
#define NTHREAD  512
#define NKC      4

typedef unsigned long long u64;
typedef unsigned int u32;

// ---------- helpers ----------
__device__ __forceinline__ u64 fma2(u64 a, u64 b, u64 c) {
    u64 d;
    asm("fma.rn.f32x2 %0, %1, %2, %3;" : "=l"(d) : "l"(a), "l"(b), "l"(c));
    return d;
}
__device__ __forceinline__ u64 pack2(float x, float y) {
    u64 r;
    asm("mov.b64 %0, {%1, %2};" : "=l"(r) : "f"(x), "f"(y));
    return r;
}
__device__ __forceinline__ void unpack2(u64 v, float& x, float& y) {
    asm("mov.b64 {%0, %1}, %2;" : "=f"(x), "=f"(y) : "l"(v));
}
__device__ __forceinline__ u32 smem_u32(const void* p) {
    u32 a;
    asm("{ .reg .u64 t; cvta.to.shared.u64 t, %1; cvt.u32.u64 %0, t; }" : "=r"(a) : "l"(p));
    return a;
}
__device__ __forceinline__ void cp_async16(char* smem_dst, const char* gsrc) {
    u32 s = smem_u32(smem_dst);
    asm volatile("cp.async.cg.shared.global [%0], [%1], 16;" :: "r"(s), "l"(gsrc));
}
__device__ __forceinline__ void cp_commit() { asm volatile("cp.async.commit_group;"); }

__device__ __forceinline__ void ldsm4(u32& r0, u32& r1, u32& r2, u32& r3, u32 addr) {
    asm volatile("ldmatrix.sync.aligned.m8n8.x4.shared.b16 {%0,%1,%2,%3}, [%4];"
                 : "=r"(r0), "=r"(r1), "=r"(r2), "=r"(r3) : "r"(addr));
}
__device__ __forceinline__ void mma16816(float* d, const u32* a, const u32* b) {
    asm volatile(
        "mma.sync.aligned.m16n8k16.row.col.f32.bf16.bf16.f32 "
        "{%0,%1,%2,%3}, {%4,%5,%6,%7}, {%8,%9}, {%0,%1,%2,%3};"
        : "+f"(d[0]), "+f"(d[1]), "+f"(d[2]), "+f"(d[3])
        : "r"(a[0]), "r"(a[1]), "r"(a[2]), "r"(a[3]), "r"(b[0]), "r"(b[1]));
}

// ---------- W2^T bf16 hi/lo images: [chunk kc][n=256][kl=64], 128B rows, XOR-16B swizzle ----------
__device__ __align__(128) unsigned short g_W2h[65536];
__device__ __align__(128) unsigned short g_W2l[65536];

__global__ void prep_w2(const float* __restrict__ W2) {
    int i = blockIdx.x * 256 + threadIdx.x;   // i = k*256 + n over W2[k][n]
    int k = i >> 8, n = i & 255;
    float w = W2[i];
    __nv_bfloat16 hb = __float2bfloat16(w);
    float hf = __bfloat162float(hb);
    __nv_bfloat16 lb = __float2bfloat16(w - hf);
    int kc = k >> 6, kl = k & 63;
    u32 off = (u32)kc * 32768u + (u32)n * 128u
            + ((((u32)kl >> 3) ^ ((u32)n & 7)) << 4) + (((u32)kl & 7) << 1);
    g_W2h[off >> 1] = __bfloat16_as_ushort(hb);
    g_W2l[off >> 1] = __bfloat16_as_ushort(lb);
}

// ---------- smem byte offsets ----------
#define SB      0         // B double buffer: 2 x (hi 32768 + lo 32768) = 131072
#define SA      131072    // A: hi 16384 + lo 16384 = 32768
#define SXS     163840    // x tile 128*12 f32 = 6144
#define SW1T    169984    // W1 transposed [j][k] f32 = 12288
#define SW3P    182272    // W3 pairs 128*12 u64 = 12288
#define SPART   194560    // partials 4*128*12 f32 = 24576
#define SB1     219136    // 1024
#define SB2     220160    // 1024
#define SB3     221184    // 64
#define SMEM_BYTES 221248

__global__ __launch_bounds__(NTHREAD, 1)
void mlp_main(const float* __restrict__ inp,
              const float* __restrict__ W1,
              const float* __restrict__ b1,
              const float* __restrict__ b2,
              const float* __restrict__ W3,
              const float* __restrict__ b3,
              float* __restrict__ out)
{
    extern __shared__ char sm[];
    float* xs   = (float*)(sm + SXS);
    float* w1t  = (float*)(sm + SW1T);
    u64*   w3p  = (u64*)  (sm + SW3P);
    float* part = (float*)(sm + SPART);
    float* b1s  = (float*)(sm + SB1);
    float* b2s  = (float*)(sm + SB2);
    float* b3s  = (float*)(sm + SB3);
    const u32 smb = smem_u32(sm);
    const int t = threadIdx.x;
    const long rowBase = (long)blockIdx.x * TROWS;

    // ---- prefetch B chunk 0 into buf0 ----
    {
        const char* srcH = (const char*)g_W2h;
        const char* srcL = (const char*)g_W2l;
#pragma unroll
        for (int i = 0; i < 4; i++) {
            int o = (t + i * NTHREAD) * 16;
            cp_async16(sm + SB + o, srcH + o);
            cp_async16(sm + SB + 32768 + o, srcL + o);
        }
        cp_commit();
    }

    // ---- staging ----
    const float* inpBlk = inp + rowBase * 12;
    for (int i = t; i < TROWS * 12; i += NTHREAD) xs[i] = inpBlk[i];
    for (int i = t; i < 3072; i += NTHREAD) { int k = i >> 8, j = i & 255; w1t[j * 12 + k] = W1[i]; }
    for (int i = t; i < 1536; i += NTHREAD) {
        int k2 = i / 12, o = i % 12;
        w3p[i] = pack2(W3[(2 * k2) * 12 + o], W3[(2 * k2 + 1) * 12 + o]);
    }
    for (int i = t; i < 256; i += NTHREAD) { b1s[i] = b1[i]; b2s[i] = b2[i]; }
    if (t < 12) b3s[t] = b3[t];
    __syncthreads();

    // per-thread layer-1 assignment: row r, 16 units starting at ub
    const int r  = t & 127;
    const int ub = (t >> 7) * 16;
    float xr[12];
#pragma unroll
    for (int k = 0; k < 12; k++) xr[k] = xs[r * 12 + k];

    // warp-level mma geometry
    const int w = t >> 5, lane = t & 31;
    const int m0 = (w & 3) * 32, n0 = (w >> 2) * 64;
    const int lt  = lane >> 3;        // tile index within ldmatrix.x4
    const int l8  = lane & 7;

    // precompute ldmatrix row addressing
    // A frags (mfrag a=0,1): row = m0 + a*16 + (lt&1)*8 + l8 ; chunk sel uses (lt>>1)
    u32 arow[2], asx[2];
#pragma unroll
    for (int a = 0; a < 2; a++) {
        u32 row = (u32)(m0 + a * 16 + ((lt & 1) << 3) + l8);
        arow[a] = row << 7;           // row * 128
        asx[a]  = row & 7;
    }
    const u32 a_kt = (u32)(lt >> 1);  // +0/+1 chunk within kstep
    // B frag-pairs (fp=0..3): row_n = n0 + fp*16 + (lt>>1)*8 + l8 ; chunk sel uses (lt&1)
    u32 brow[4], bsx[4];
#pragma unroll
    for (int fp = 0; fp < 4; fp++) {
        u32 row = (u32)(n0 + fp * 16 + ((lt >> 1) << 3) + l8);
        brow[fp] = row << 7;
        bsx[fp]  = row & 7;
    }
    const u32 b_kt = (u32)(lt & 1);

    float acc[2][8][4];
#pragma unroll
    for (int a = 0; a < 2; a++)
#pragma unroll
        for (int f = 0; f < 8; f++)
#pragma unroll
            for (int q = 0; q < 4; q++) acc[a][f][q] = 0.0f;

    // ---- main loop over 4 K-chunks of 64 ----
    for (int c = 0; c < NKC; c++) {
        if (c < NKC - 1) {
            const char* srcH = (const char*)g_W2h + (c + 1) * 32768;
            const char* srcL = (const char*)g_W2l + (c + 1) * 32768;
            char* dst = sm + SB + ((c + 1) & 1) * 65536;
#pragma unroll
            for (int i = 0; i < 4; i++) {
                int o = (t + i * NTHREAD) * 16;
                cp_async16(dst + o, srcH + o);
                cp_async16(dst + 32768 + o, srcL + o);
            }
            cp_commit();
        }

        // layer 1: compute A chunk (units c*64+ub .. +15), split bf16 hi/lo, swizzled store
        {
            char* ah = sm + SA;
            char* al = sm + SA + 16384;
#pragma unroll
            for (int i = 0; i < 8; i++) {
                const int kl0 = ub + 2 * i;
                const int j = c * 64 + kl0;
                const float* wa = w1t + j * 12;
                const float* wb = w1t + (j + 1) * 12;
                float a0 = b1s[j], a1 = b1s[j + 1];
#pragma unroll
                for (int k = 0; k < 12; k++) {
                    a0 = fmaf(xr[k], wa[k], a0);
                    a1 = fmaf(xr[k], wb[k], a1);
                }
                a0 = fmaxf(a0, 0.0f); a1 = fmaxf(a1, 0.0f);
                __nv_bfloat16 h0 = __float2bfloat16(a0), h1 = __float2bfloat16(a1);
                __nv_bfloat16 l0 = __float2bfloat16(a0 - __bfloat162float(h0));
                __nv_bfloat16 l1 = __float2bfloat16(a1 - __bfloat162float(h1));
                u32 hw = (u32)__bfloat16_as_ushort(h0) | ((u32)__bfloat16_as_ushort(h1) << 16);
                u32 lw = (u32)__bfloat16_as_ushort(l0) | ((u32)__bfloat16_as_ushort(l1) << 16);
                u32 off = ((u32)r << 7) + (((u32)(kl0 >> 3) ^ ((u32)r & 7)) << 4) + (((u32)kl0 << 1) & 15);
                *(u32*)(ah + off) = hw;
                *(u32*)(al + off) = lw;
            }
        }

        if (c < NKC - 1) asm volatile("cp.async.wait_group 1;" ::: "memory");
        else             asm volatile("cp.async.wait_group 0;" ::: "memory");
        __syncthreads();   // A written, B(c) resident

        const u32 pAh = smb + SA;
        const u32 pAl = smb + SA + 16384;
        const u32 pBh = smb + SB + (u32)(c & 1) * 65536u;
        const u32 pBl = pBh + 32768u;

#pragma unroll
        for (int ks = 0; ks < 4; ks++) {
            const u32 kchunk = (u32)(ks << 1);
            u32 Ah[2][4], Al[2][4], B[4][4];
#pragma unroll
            for (int a = 0; a < 2; a++) {
                u32 ad = arow[a] + (((kchunk + a_kt) ^ asx[a]) << 4);
                ldsm4(Ah[a][0], Ah[a][1], Ah[a][2], Ah[a][3], pAh + ad);
                ldsm4(Al[a][0], Al[a][1], Al[a][2], Al[a][3], pAl + ad);
            }
#pragma unroll
            for (int fp = 0; fp < 4; fp++) {
                u32 bd = brow[fp] + (((kchunk + b_kt) ^ bsx[fp]) << 4);
                ldsm4(B[fp][0], B[fp][1], B[fp][2], B[fp][3], pBh + bd);
            }
            // Ah*Bh and Al*Bh
#pragma unroll
            for (int a = 0; a < 2; a++)
#pragma unroll
                for (int fp = 0; fp < 4; fp++) {
                    mma16816(acc[a][2 * fp],     Ah[a], &B[fp][0]);
                    mma16816(acc[a][2 * fp + 1], Ah[a], &B[fp][2]);
                    mma16816(acc[a][2 * fp],     Al[a], &B[fp][0]);
                    mma16816(acc[a][2 * fp + 1], Al[a], &B[fp][2]);
                }
            // Bl, then Ah*Bl
#pragma unroll
            for (int fp = 0; fp < 4; fp++) {
                u32 bd = brow[fp] + (((kchunk + b_kt) ^ bsx[fp]) << 4);
                ldsm4(B[fp][0], B[fp][1], B[fp][2], B[fp][3], pBl + bd);
            }
#pragma unroll
            for (int a = 0; a < 2; a++)
#pragma unroll
                for (int fp = 0; fp < 4; fp++) {
                    mma16816(acc[a][2 * fp],     Ah[a], &B[fp][0]);
                    mma16816(acc[a][2 * fp + 1], Ah[a], &B[fp][2]);
                }
        }
        __syncthreads();   // all warps done reading A/B before next overwrite
    }

    // ---- epilogue: bias + relu + layer-3 partials + quad reduce ----
    {
        const int nw = w >> 2;
        const int cbase = n0 + (lane & 3) * 2;
#pragma unroll
        for (int a = 0; a < 2; a++) {
#pragma unroll
            for (int h = 0; h < 2; h++) {
                u64 p[12];
#pragma unroll
                for (int o = 0; o < 12; o++) p[o] = 0;
#pragma unroll
                for (int f = 0; f < 8; f++) {
                    const int col = cbase + 8 * f;
                    float h0 = fmaxf(acc[a][f][2 * h]     + b2s[col],     0.0f);
                    float h1 = fmaxf(acc[a][f][2 * h + 1] + b2s[col + 1], 0.0f);
                    const u64 hh = pack2(h0, h1);
                    const u64* wv = w3p + (col >> 1) * 12;
#pragma unroll
                    for (int o = 0; o < 12; o++) p[o] = fma2(wv[o], hh, p[o]);
                }
                float v[12];
#pragma unroll
                for (int o = 0; o < 12; o++) {
                    float lo, hi;
                    unpack2(p[o], lo, hi);
                    v[o] = lo + hi;
                    v[o] += __shfl_xor_sync(0xffffffffu, v[o], 1);
                    v[o] += __shfl_xor_sync(0xffffffffu, v[o], 2);
                }
                if ((lane & 3) == 0) {
                    const int row = m0 + a * 16 + h * 8 + (lane >> 2);
                    float* dst = part + (nw * 128 + row) * 12;
#pragma unroll
                    for (int o = 0; o < 12; o++) dst[o] = v[o];
                }
            }
        }
    }
    __syncthreads();

    // ---- constraint epilogue: threads 0..127, one row each ----
    if (t < TROWS) {
        const float* xi = xs + t * 12;
        float xo[12];
#pragma unroll
        for (int o = 0; o < 12; o++) {
            xo[o] = b3s[o] + part[t * 12 + o] + part[(128 + t) * 12 + o]
                  + part[(256 + t) * 12 + o] + part[(384 + t) * 12 + o];
        }

        float p0 = tanhf(xo[0]), p1 = tanhf(xo[1]), p2 = tanhf(xo[2]);
        float v0 = tanhf(xo[3]), v1 = tanhf(xo[4]), v2 = tanhf(xo[5]);
        float pts = 1.0f / (1.0f + expf(-xo[6]));
        float c0 = tanhf(xo[7]), c1 = tanhf(xo[8]), c2 = tanhf(xo[9]);
        float s0 = tanhf(xo[10]), s1 = tanhf(xo[11]);

        float dist = sqrtf(p0 * p0 + p1 * p1 + p2 * p2);
        float pinv = (dist > 1.0f) ? (1.0f / dist) : 1.0f;
        p0 *= pinv; p1 *= pinv; p2 *= pinv;

        const float prev = xi[6];
        float ptsc = (pts > 1.0f) ? 1.0f : pts;
        ptsc = (pts < prev) ? prev : ptsc;

        const float d0 = c0 - xi[7], d1 = c1 - xi[8], d2 = c2 - xi[9];
        const float e0 = xi[0] - xi[7], e1 = xi[1] - xi[8], e2 = xi[2] - xi[9];
        const float en = sqrtf(e0 * e0 + e1 * e1 + e2 * e2);
        const float n0f = e0 / en, n1f = e1 / en, n2f = e2 / en;
        const float dd = d0 * e0 + d1 * e1 + d2 * e2;
        const float o0 = (dd > 0.0f) ? (c0 - n0f) : c0;
        const float o1 = (dd > 0.0f) ? (c1 - n1f) : c1;
        const float o2 = (dd > 0.0f) ? (c2 - n2f) : c2;
        const float cd = sqrtf(o0 * o0 + o1 * o1 + o2 * o2);
        float q0, q1, q2;
        if (cd > 1.0f) { const float ci = 1.0f / cd; q0 = o0 * ci; q1 = o1 * ci; q2 = o2 * ci; }
        else           { q0 = c0; q1 = c1; q2 = c2; }

        const float sn = sqrtf(s0 * s0 + s1 * s1);
        s0 /= sn; s1 /= sn;

        float* op = out + (rowBase + t) * 12;
        float4* ov = reinterpret_cast<float4*>(op);
        ov[0] = make_float4(p0, p1, p2, v0);
        ov[1] = make_float4(v1, v2, ptsc, q0);
        ov[2] = make_float4(q1, q2, s0, s1);
    }
}

extern "C" void kernel_launch(void* const* d_in, const int* in_sizes, int n_in,
                              void* d_out, int out_size)
{
    (void)in_sizes; (void)n_in; (void)out_size;
    const float* inp = (const float*)d_in[0];
    const float* W1  = (const float*)d_in[1];
    const float* b1  = (const float*)d_in[2];
    const float* W2  = (const float*)d_in[3];
    const float* b2  = (const float*)d_in[4];
    const float* W3  = (const float*)d_in[5];
    const float* b3  = (const float*)d_in[6];
    float* out = (float*)d_out;

    prep_w2<<<256, 256>>>(W2);

    cudaFuncSetAttribute(mlp_main, cudaFuncAttributeMaxDynamicSharedMemorySize, SMEM_BYTES);
    mlp_main<<<BATCH / TROWS, NTHREAD, SMEM_BYTES>>>(inp, W1, b1, b2, W3, b3, out);
}

// round 6
// speedup vs baseline: 3.5696x; 1.0411x over previous
#include <cuda_runtime.h>
#include <cuda_bf16.h>
#include <math.h>
#include <stdint.h>

// Fused ConstrainedMLP: 262144 x (12 -> 256 relu -> 256 relu -> 12) + constraints.
// R6: layer 2 via mma.sync.m16n8k16 bf16, 3-term hi/lo split. A (h1) computed ONCE
// into resident smem images; mma mainloop is pure ldsm+mma over 8 B half-chunks
// (32 k each), cp.async double-buffered. CTA: 128 rows, 512 threads (16 warps 4Mx4N).

#define BATCH    262144
#define TROWS    128
#define NTHREAD  512

typedef unsigned long long u64;
typedef unsigned int u32;

// ---------- helpers ----------
__device__ __forceinline__ u64 fma2(u64 a, u64 b, u64 c) {
    u64 d;
    asm("fma.rn.f32x2 %0, %1, %2, %3;" : "=l"(d) : "l"(a), "l"(b), "l"(c));
    return d;
}
__device__ __forceinline__ u64 pack2(float x, float y) {
    u64 r;
    asm("mov.b64 %0, {%1, %2};" : "=l"(r) : "f"(x), "f"(y));
    return r;
}
__device__ __forceinline__ void unpack2(u64 v, float& x, float& y) {
    asm("mov.b64 {%0, %1}, %2;" : "=f"(x), "=f"(y) : "l"(v));
}
__device__ __forceinline__ u32 smem_u32(const void* p) {
    u32 a;
    asm("{ .reg .u64 t; cvta.to.shared.u64 t, %1; cvt.u32.u64 %0, t; }" : "=r"(a) : "l"(p));
    return a;
}
__device__ __forceinline__ void cp_async16(char* smem_dst, const char* gsrc) {
    u32 s = smem_u32(smem_dst);
    asm volatile("cp.async.cg.shared.global [%0], [%1], 16;" :: "r"(s), "l"(gsrc));
}
__device__ __forceinline__ void cp_commit() { asm volatile("cp.async.commit_group;"); }

__device__ __forceinline__ void ldsm4(u32& r0, u32& r1, u32& r2, u32& r3, u32 addr) {
    asm volatile("ldmatrix.sync.aligned.m8n8.x4.shared.b16 {%0,%1,%2,%3}, [%4];"
                 : "=r"(r0), "=r"(r1), "=r"(r2), "=r"(r3) : "r"(addr));
}
__device__ __forceinline__ void mma16816(float* d, const u32* a, const u32* b) {
    asm volatile(
        "mma.sync.aligned.m16n8k16.row.col.f32.bf16.bf16.f32 "
        "{%0,%1,%2,%3}, {%4,%5,%6,%7}, {%8,%9}, {%0,%1,%2,%3};"
        : "+f"(d[0]), "+f"(d[1]), "+f"(d[2]), "+f"(d[3])
        : "r"(a[0]), "r"(a[1]), "r"(a[2]), "r"(a[3]), "r"(b[0]), "r"(b[1]));
}

// ---------- W2^T bf16 hi/lo images ----------
// 8 half-chunks (32 k each). Per half-chunk: n in [0,256), 4 x 16B k-units per n.
// Two n-rows share each 128B line: line = n&127, 16B slot s = (u + 4*(n>>7)) ^ (n&7).
// -> ldmatrix over 8 consecutive n is bank-conflict-free.
__device__ __align__(128) unsigned short g_W2h[65536];
__device__ __align__(128) unsigned short g_W2l[65536];

__global__ void prep_w2(const float* __restrict__ W2) {
    int i = blockIdx.x * 256 + threadIdx.x;   // i = k*256 + n over W2[k][n]
    int k = i >> 8, n = i & 255;
    float w = W2[i];
    __nv_bfloat16 hb = __float2bfloat16(w);
    __nv_bfloat16 lb = __float2bfloat16(w - __bfloat162float(hb));
    u32 hc = (u32)k >> 5, kl = (u32)k & 31;
    u32 s = ((kl >> 3) + (((u32)n >> 7) << 2)) ^ ((u32)n & 7);
    u32 off = hc * 16384u + ((u32)n & 127) * 128u + s * 16u + (kl & 7) * 2u;
    g_W2h[off >> 1] = __bfloat16_as_ushort(hb);
    g_W2l[off >> 1] = __bfloat16_as_ushort(lb);
}

// ---------- smem byte offsets ----------
#define SA      0         // A: hi 4x16384 @0, lo 4x16384 @65536 -> 131072
#define SB      131072    // B double buffer: 2 x (hi 16384 + lo 16384) = 65536
#define SXS     196608    // x tile 128*12 f32 = 6144
#define SW3P    202752    // W3 pairs 128*12 u64 = 12288
#define SB1     215040    // 1024
#define SB2     216064    // 1024
#define SB3     217088    // 64
#define SMEM_BYTES 217152
#define SW1P    (SB + 32768)   // W1 pairs (12288 B), aliased into B buf1 (dead after layer 1)
#define SPART   SB             // layer-3 partials (24576 B), aliased into B buf0 (after mma)

__global__ __launch_bounds__(NTHREAD, 1)
void mlp_main(const float* __restrict__ inp,
              const float* __restrict__ W1,
              const float* __restrict__ b1,
              const float* __restrict__ b2,
              const float* __restrict__ W3,
              const float* __restrict__ b3,
              float* __restrict__ out)
{
    extern __shared__ char sm[];
    float* xs   = (float*)(sm + SXS);
    u64*   w3p  = (u64*)  (sm + SW3P);
    u64*   w1p  = (u64*)  (sm + SW1P);
    float* part = (float*)(sm + SPART);
    float* b1s  = (float*)(sm + SB1);
    float* b2s  = (float*)(sm + SB2);
    float* b3s  = (float*)(sm + SB3);
    const u32 smb = smem_u32(sm);
    const int t = threadIdx.x;
    const long rowBase = (long)blockIdx.x * TROWS;

    // ---- prefetch B half-chunk 0 into buf0 ----
    {
        const char* srcH = (const char*)g_W2h;
        const char* srcL = (const char*)g_W2l;
#pragma unroll
        for (int i = 0; i < 2; i++) {
            int o = (t + i * NTHREAD) * 16;
            cp_async16(sm + SB + o, srcH + o);
            cp_async16(sm + SB + 16384 + o, srcL + o);
        }
        cp_commit();
    }

    // ---- staging ----
    const float* inpBlk = inp + rowBase * 12;
    for (int i = t; i < TROWS * 12; i += NTHREAD) xs[i] = inpBlk[i];
    for (int i = t; i < 1536; i += NTHREAD) {        // W1 pairs: [j/2][k] -> (W1[k][2jp], W1[k][2jp+1])
        int jp = i / 12, k = i % 12;
        w1p[i] = pack2(W1[k * 256 + 2 * jp], W1[k * 256 + 2 * jp + 1]);
    }
    for (int i = t; i < 1536; i += NTHREAD) {        // W3 pairs
        int k2 = i / 12, o = i % 12;
        w3p[i] = pack2(W3[(2 * k2) * 12 + o], W3[(2 * k2 + 1) * 12 + o]);
    }
    for (int i = t; i < 256; i += NTHREAD) { b1s[i] = b1[i]; b2s[i] = b2[i]; }
    if (t < 12) b3s[t] = b3[t];
    __syncthreads();

    // ---- layer 1: thread t -> row r = t&127, units [ug*64, ug*64+64) = chunk ug ----
    {
        const int r = t & 127, ug = t >> 7;
        u64 xx[12];
#pragma unroll
        for (int k = 0; k < 12; k++) { float x = xs[r * 12 + k]; xx[k] = pack2(x, x); }
        char* ahc = sm + SA + ug * 16384;
        char* alc = sm + SA + 65536 + ug * 16384;
#pragma unroll 4
        for (int i = 0; i < 32; i++) {
            const int kl0 = 2 * i;
            const int j = ug * 64 + kl0;
            const u64* wp = w1p + (j >> 1) * 12;
            u64 acc2 = pack2(b1s[j], b1s[j + 1]);
#pragma unroll
            for (int k = 0; k < 12; k++) acc2 = fma2(wp[k], xx[k], acc2);
            float a0, a1;
            unpack2(acc2, a0, a1);
            a0 = fmaxf(a0, 0.0f); a1 = fmaxf(a1, 0.0f);
            __nv_bfloat16 h0 = __float2bfloat16(a0), h1 = __float2bfloat16(a1);
            __nv_bfloat16 l0 = __float2bfloat16(a0 - __bfloat162float(h0));
            __nv_bfloat16 l1 = __float2bfloat16(a1 - __bfloat162float(h1));
            u32 hw = (u32)__bfloat16_as_ushort(h0) | ((u32)__bfloat16_as_ushort(h1) << 16);
            u32 lw = (u32)__bfloat16_as_ushort(l0) | ((u32)__bfloat16_as_ushort(l1) << 16);
            u32 off = ((u32)r << 7) + ((((u32)(kl0 >> 3)) ^ ((u32)r & 7)) << 4) + (((u32)kl0 & 7) << 1);
            *(u32*)(ahc + off) = hw;
            *(u32*)(alc + off) = lw;
        }
    }
    // NOTE: no standalone barrier here; the loop-top __syncthreads of hc=0 covers
    // A visibility AND w1p death before buf1 prefetch.

    // ---- warp mma geometry ----
    const int w = t >> 5, lane = t & 31;
    const int m0 = (w & 3) * 32, n0 = (w >> 2) * 64;
    const int lt = lane >> 3, l8 = lane & 7;

    u32 arow[2], asx[2];
#pragma unroll
    for (int a = 0; a < 2; a++) {
        u32 row = (u32)(m0 + a * 16 + ((lt & 1) << 3) + l8);
        arow[a] = row << 7;
        asx[a]  = row & 7;
    }
    const u32 a_kt = (u32)(lt >> 1);
    u32 bline[4], bx[4];
    const u32 bhi = ((u32)n0 >> 7) << 2;
#pragma unroll
    for (int fp = 0; fp < 4; fp++) {
        u32 n = (u32)(n0 + fp * 16 + ((lt >> 1) << 3) + l8);
        bline[fp] = (n & 127) << 7;
        bx[fp]    = n & 7;
    }
    const u32 b_kt = (u32)(lt & 1);

    float acc[2][8][4];
#pragma unroll
    for (int a = 0; a < 2; a++)
#pragma unroll
        for (int f = 0; f < 8; f++)
#pragma unroll
            for (int q = 0; q < 4; q++) acc[a][f][q] = 0.0f;

    // ---- mma mainloop: 8 half-chunks of 32 k ----
    for (int hc = 0; hc < 8; hc++) {
        asm volatile("cp.async.wait_group 0;" ::: "memory");
        __syncthreads();                      // B(hc) visible; prev buffer consumed; (hc=0: A+w1p barrier)
        if (hc < 7) {
            const char* srcH = (const char*)g_W2h + (hc + 1) * 16384;
            const char* srcL = (const char*)g_W2l + (hc + 1) * 16384;
            char* dst = sm + SB + ((hc + 1) & 1) * 32768;
#pragma unroll
            for (int i = 0; i < 2; i++) {
                int o = (t + i * NTHREAD) * 16;
                cp_async16(dst + o, srcH + o);
                cp_async16(dst + 16384 + o, srcL + o);
            }
            cp_commit();
        }

        const u32 pBh = smb + SB + (u32)(hc & 1) * 32768u;
        const u32 pBl = pBh + 16384u;
        const u32 pAh = smb + SA + (u32)(hc >> 1) * 16384u;
        const u32 pAl = pAh + 65536u;

#pragma unroll
        for (int ks2 = 0; ks2 < 2; ks2++) {
            const u32 ktA = (u32)(((hc & 1) * 2 + ks2) * 2) + a_kt;
            const u32 uB  = (u32)(ks2 * 2) + b_kt;
            u32 Ah[2][4], Al[2][4], B[4][4];
#pragma unroll
            for (int a = 0; a < 2; a++) {
                u32 ad = arow[a] + ((ktA ^ asx[a]) << 4);
                ldsm4(Ah[a][0], Ah[a][1], Ah[a][2], Ah[a][3], pAh + ad);
                ldsm4(Al[a][0], Al[a][1], Al[a][2], Al[a][3], pAl + ad);
            }
#pragma unroll
            for (int fp = 0; fp < 4; fp++) {
                u32 bd = bline[fp] + (((uB + bhi) ^ bx[fp]) << 4);
                ldsm4(B[fp][0], B[fp][1], B[fp][2], B[fp][3], pBh + bd);
            }
#pragma unroll
            for (int a = 0; a < 2; a++)
#pragma unroll
                for (int fp = 0; fp < 4; fp++) {
                    mma16816(acc[a][2 * fp],     Ah[a], &B[fp][0]);
                    mma16816(acc[a][2 * fp + 1], Ah[a], &B[fp][2]);
                    mma16816(acc[a][2 * fp],     Al[a], &B[fp][0]);
                    mma16816(acc[a][2 * fp + 1], Al[a], &B[fp][2]);
                }
#pragma unroll
            for (int fp = 0; fp < 4; fp++) {
                u32 bd = bline[fp] + (((uB + bhi) ^ bx[fp]) << 4);
                ldsm4(B[fp][0], B[fp][1], B[fp][2], B[fp][3], pBl + bd);
            }
#pragma unroll
            for (int a = 0; a < 2; a++)
#pragma unroll
                for (int fp = 0; fp < 4; fp++) {
                    mma16816(acc[a][2 * fp],     Ah[a], &B[fp][0]);
                    mma16816(acc[a][2 * fp + 1], Ah[a], &B[fp][2]);
                }
        }
    }

    // ---- epilogue: bias + relu + layer-3 partials + quad reduce (part aliases B buf0) ----
    {
        const int nw = w >> 2;
        const int cbase = n0 + (lane & 3) * 2;
#pragma unroll
        for (int a = 0; a < 2; a++) {
#pragma unroll
            for (int h = 0; h < 2; h++) {
                u64 p[12];
#pragma unroll
                for (int o = 0; o < 12; o++) p[o] = 0;
#pragma unroll
                for (int f = 0; f < 8; f++) {
                    const int col = cbase + 8 * f;
                    float h0 = fmaxf(acc[a][f][2 * h]     + b2s[col],     0.0f);
                    float h1 = fmaxf(acc[a][f][2 * h + 1] + b2s[col + 1], 0.0f);
                    const u64 hh = pack2(h0, h1);
                    const u64* wv = w3p + (col >> 1) * 12;
#pragma unroll
                    for (int o = 0; o < 12; o++) p[o] = fma2(wv[o], hh, p[o]);
                }
                float v[12];
#pragma unroll
                for (int o = 0; o < 12; o++) {
                    float lo, hi;
                    unpack2(p[o], lo, hi);
                    v[o] = lo + hi;
                    v[o] += __shfl_xor_sync(0xffffffffu, v[o], 1);
                    v[o] += __shfl_xor_sync(0xffffffffu, v[o], 2);
                }
                if ((lane & 3) == 0) {
                    const int row = m0 + a * 16 + h * 8 + (lane >> 2);
                    float* dst = part + (nw * 128 + row) * 12;
#pragma unroll
                    for (int o = 0; o < 12; o++) dst[o] = v[o];
                }
            }
        }
    }
    __syncthreads();

    // ---- constraint epilogue: threads 0..127, one row each ----
    if (t < TROWS) {
        const float* xi = xs + t * 12;
        float xo[12];
#pragma unroll
        for (int o = 0; o < 12; o++) {
            xo[o] = b3s[o] + part[t * 12 + o] + part[(128 + t) * 12 + o]
                  + part[(256 + t) * 12 + o] + part[(384 + t) * 12 + o];
        }

        float p0 = tanhf(xo[0]), p1 = tanhf(xo[1]), p2 = tanhf(xo[2]);
        float v0 = tanhf(xo[3]), v1 = tanhf(xo[4]), v2 = tanhf(xo[5]);
        float pts = 1.0f / (1.0f + expf(-xo[6]));
        float c0 = tanhf(xo[7]), c1 = tanhf(xo[8]), c2 = tanhf(xo[9]);
        float s0 = tanhf(xo[10]), s1 = tanhf(xo[11]);

        float dist = sqrtf(p0 * p0 + p1 * p1 + p2 * p2);
        float pinv = (dist > 1.0f) ? (1.0f / dist) : 1.0f;
        p0 *= pinv; p1 *= pinv; p2 *= pinv;

        const float prev = xi[6];
        float ptsc = (pts > 1.0f) ? 1.0f : pts;
        ptsc = (pts < prev) ? prev : ptsc;

        const float d0 = c0 - xi[7], d1 = c1 - xi[8], d2 = c2 - xi[9];
        const float e0 = xi[0] - xi[7], e1 = xi[1] - xi[8], e2 = xi[2] - xi[9];
        const float en = sqrtf(e0 * e0 + e1 * e1 + e2 * e2);
        const float n0f = e0 / en, n1f = e1 / en, n2f = e2 / en;
        const float dd = d0 * e0 + d1 * e1 + d2 * e2;
        const float o0 = (dd > 0.0f) ? (c0 - n0f) : c0;
        const float o1 = (dd > 0.0f) ? (c1 - n1f) : c1;
        const float o2 = (dd > 0.0f) ? (c2 - n2f) : c2;
        const float cd = sqrtf(o0 * o0 + o1 * o1 + o2 * o2);
        float q0, q1, q2;
        if (cd > 1.0f) { const float ci = 1.0f / cd; q0 = o0 * ci; q1 = o1 * ci; q2 = o2 * ci; }
        else           { q0 = c0; q1 = c1; q2 = c2; }

        const float sn = sqrtf(s0 * s0 + s1 * s1);
        s0 /= sn; s1 /= sn;

        float* op = out + (rowBase + t) * 12;
        float4* ov = reinterpret_cast<float4*>(op);
        ov[0] = make_float4(p0, p1, p2, v0);
        ov[1] = make_float4(v1, v2, ptsc, q0);
        ov[2] = make_float4(q1, q2, s0, s1);
    }
}

extern "C" void kernel_launch(void* const* d_in, const int* in_sizes, int n_in,
                              void* d_out, int out_size)
{
    (void)in_sizes; (void)n_in; (void)out_size;
    const float* inp = (const float*)d_in[0];
    const float* W1  = (const float*)d_in[1];
    const float* b1  = (const float*)d_in[2];
    const float* W2  = (const float*)d_in[3];
    const float* b2  = (const float*)d_in[4];
    const float* W3  = (const float*)d_in[5];
    const float* b3  = (const float*)d_in[6];
    float* out = (float*)d_out;

    prep_w2<<<256, 256>>>(W2);

    cudaFuncSetAttribute(mlp_main, cudaFuncAttributeMaxDynamicSharedMemorySize, SMEM_BYTES);
    mlp_main<<<BATCH / TROWS, NTHREAD, SMEM_BYTES>>>(inp, W1, b1, b2, W3, b3, out);
}